// round 4
// baseline (speedup 1.0000x reference)
#include <cuda_runtime.h>
#include <cuda_fp16.h>

// M is [512, 65536] fp32. Sinkhorn; trip count in {1, 51, 100}; this input exits at 1.
#define NR    512
#define NC    65536
#define GRID  128              // <= SM count: wave-1 co-residency guaranteed
#define TPB   1024             // 32 warps/SM -> 2x memory parallelism vs R3
#define CPB   512              // columns per block (full column stripe, all rows)
#define HR    256              // rows per thread-half

// Persistent scratch (__device__ globals per allocation rule)
__device__ __half   g_K[(size_t)NR * NC];       // 64 MB fp16 kernel matrix
__device__ float    g_sPart[2][GRID * NR];      // parity-double-buffered row partials
__device__ float    g_errPart[GRID];
__device__ float    g_lossPart[GRID];
__device__ int      g_done;
__device__ unsigned g_bar = 0;
__device__ volatile unsigned g_gen = 0;         // monotone across graph replays

// Grid barrier: GRID <= #SMs -> cannot deadlock. Spin cap = escape hatch only.
__device__ __forceinline__ void gsync(unsigned &phase) {
    __syncthreads();
    if (threadIdx.x == 0) {
        ++phase;
        __threadfence();
        if (atomicAdd(&g_bar, 1u) == GRID - 1u) {
            g_bar = 0u;
            __threadfence();
            g_gen = phase;
        } else {
            unsigned spins = 0;
            while (g_gen < phase) {
                __nanosleep(64);
                if (++spins > (1u << 18)) break;
            }
        }
    }
    __syncthreads();
}

__device__ __forceinline__ float blockReduce1024(float x, float* sh) {
    const int t = threadIdx.x;
    sh[t] = x; __syncthreads();
    if (t < 512) sh[t] += sh[t + 512];
    __syncthreads();
    if (t < 256) sh[t] += sh[t + 256];
    __syncthreads();
    if (t < 128) sh[t] += sh[t + 128];
    __syncthreads();
    if (t < 64)  sh[t] += sh[t + 64];
    __syncthreads();
    if (t < 32) {
        float v = sh[t] + sh[t + 32];
        #pragma unroll
        for (int o = 16; o; o >>= 1) v += __shfl_down_sync(0xffffffffu, v, o);
        if (t == 0) sh[0] = v;
    }
    __syncthreads();
    float r = sh[0];
    __syncthreads();
    return r;
}

__global__ void __launch_bounds__(TPB, 1)
sinkhorn_all(const float* __restrict__ M, float* __restrict__ out) {
    __shared__ float sh[TPB];
    __shared__ float sh2[TPB];
    __shared__ float sh_u[NR];     // full u, replicated per block
    __shared__ float sh_v[CPB];    // this block's v stripe
    const int tid = threadIdx.x;
    const int bid = blockIdx.x;
    unsigned phase = g_gen;        // continue barrier generation across graph replays

    const int jc = tid & (CPB - 1);           // column within stripe
    const int h  = tid >> 9;                  // row half (0: rows 0..255, 1: 256..511)
    const int j  = bid * CPB + jc;
    const float* Mj = M + (size_t)h * HR * NC + j;

    // ===== pass A (c=1) fused with exp precompute: t_j = (1/NR) * sum_i K_ij =====
    {
        float t = 0.0f;
        __half* Kj = g_K + (size_t)h * HR * NC + j;
        #pragma unroll 8
        for (int r = 0; r < HR; ++r) {
            float m = __ldcs(&Mj[(size_t)r * NC]);       // streaming: keep K in L2
            float k = __expf(-20.0f * m);
            Kj[(size_t)r * NC] = __float2half(k);
            t += k;
        }
        sh[tid] = t; __syncthreads();
        if (tid < CPB) {
            float tt = (sh[tid] + sh[tid + CPB]) * (1.0f / NR);
            sh_v[tid] = (1.0f / NC) / (tt + 1e-16f);
        }
        __syncthreads();
    }

    // ---- phase C: s_i = sum_{j in stripe} K_ij v_j -> partials; then every
    // block reduces the full u locally (no g_u round-trip, 1 gsync total).
    #define PHASE_C(par)                                                           \
    {                                                                              \
        const int wid = tid >> 5, lane = tid & 31;                                 \
        _Pragma("unroll")                                                          \
        for (int rr = 0; rr < 16; ++rr) {                                          \
            const int row = wid * 16 + rr;                                         \
            const uint4* kp = (const uint4*)(g_K + (size_t)row * NC + bid * CPB);  \
            float s = 0.0f;                                                        \
            _Pragma("unroll")                                                      \
            for (int c = lane; c < 64; c += 32) {                                  \
                uint4 kk = kp[c];                                                  \
                const __half2* kh = (const __half2*)&kk;                           \
                const float4* vv4 = (const float4*)&sh_v[c * 8];                   \
                float4 va = vv4[0], vb = vv4[1];                                   \
                float2 k0 = __half22float2(kh[0]);                                 \
                float2 k1 = __half22float2(kh[1]);                                 \
                float2 k2 = __half22float2(kh[2]);                                 \
                float2 k3 = __half22float2(kh[3]);                                 \
                s = fmaf(k0.x, va.x, s); s = fmaf(k0.y, va.y, s);                  \
                s = fmaf(k1.x, va.z, s); s = fmaf(k1.y, va.w, s);                  \
                s = fmaf(k2.x, vb.x, s); s = fmaf(k2.y, vb.y, s);                  \
                s = fmaf(k3.x, vb.z, s); s = fmaf(k3.y, vb.w, s);                  \
            }                                                                      \
            _Pragma("unroll")                                                      \
            for (int o = 16; o; o >>= 1) s += __shfl_down_sync(0xffffffffu, s, o); \
            if (lane == 0) g_sPart[par][bid * NR + row] = s;                       \
        }                                                                          \
        gsync(phase);                                                              \
        {                                                                          \
            float su = 0.0f;                                                       \
            _Pragma("unroll 8")                                                    \
            for (int b = h * 64; b < h * 64 + 64; ++b)                             \
                su += __ldcg(&g_sPart[par][b * NR + jc]);                          \
            sh[tid] = su; __syncthreads();                                         \
            if (tid < NR)                                                          \
                sh_u[tid] = (1.0f / NR) / ((sh[tid] + sh[tid + 512]) + 1e-16f);    \
            __syncthreads();                                                       \
        }                                                                          \
    }

    // ---- fused err+loss pass (fp32 exp from M): t' = K^T u, err, loss; if
    // converged, block 0 writes out; else v <- b/(t'+eps) becomes next v.
    #define FUSED_ERR(done_var)                                                    \
    {                                                                              \
        float tp = 0.0f, la = 0.0f;                                                \
        _Pragma("unroll 8")                                                        \
        for (int r = 0; r < HR; ++r) {                                             \
            float m = __ldcs(&Mj[(size_t)r * NC]);                                 \
            float k = __expf(-20.0f * m);                                          \
            float u = sh_u[h * HR + r];                                            \
            tp = fmaf(k, u, tp);                                                   \
            la = fmaf(k * m, u, la);                                               \
        }                                                                          \
        sh[tid] = tp; sh2[tid] = la; __syncthreads();                              \
        float errj = 0.0f, lossj = 0.0f, vn = 0.0f;                                \
        if (tid < CPB) {                                                           \
            float T = sh[tid] + sh[tid + CPB];                                     \
            float L = sh2[tid] + sh2[tid + CPB];                                   \
            float v = sh_v[tid];                                                   \
            errj  = fabsf(v * T - (1.0f / NC));                                    \
            lossj = v * L;                                                         \
            vn = (1.0f / NC) / (T + 1e-16f);                                       \
        }                                                                          \
        __syncthreads();                                                           \
        float eb = blockReduce1024(errj, sh);                                      \
        float lb = blockReduce1024(lossj, sh);                                     \
        if (tid == 0) { g_errPart[bid] = eb; g_lossPart[bid] = lb; }               \
        gsync(phase);                                                              \
        if (bid == 0) {                                                            \
            float ep = (tid < GRID) ? __ldcg(&g_errPart[tid]) : 0.0f;              \
            float et = blockReduce1024(ep, sh);                                    \
            int dn = (et <= 0.005f);                                               \
            if (dn) {                                                              \
                float lp = (tid < GRID) ? __ldcg(&g_lossPart[tid]) : 0.0f;         \
                float lt = blockReduce1024(lp, sh);                                \
                if (tid == 0) out[0] = 100.0f * lt;                                \
            }                                                                      \
            if (tid == 0) g_done = dn;                                             \
        }                                                                          \
        gsync(phase);                                                              \
        if (tid < CPB) sh_v[tid] = vn;                                             \
        __syncthreads();                                                           \
        done_var = __ldcg(&g_done);                                                \
    }

    // ===== c = 1: phase C -> u_1; err check (fused with loss) =====
    PHASE_C(0);
    int done;
    FUSED_ERR(done);
    if (done) return;                        // trip-1 fast path (3 gsyncs total)

    // ===== c = 2..100 =====
    int par = 1;
    for (int c = 2; c <= 100; ++c) {
        if (c > 2 && c != 52) {
            // phase A: t_j = sum_i K_ij u_i (fp16 K); v_j = b/(t+eps)
            float t = 0.0f;
            const __half* kc = g_K + (size_t)h * HR * NC + j;
            #pragma unroll 8
            for (int r = 0; r < HR; ++r)
                t = fmaf(__half2float(kc[(size_t)r * NC]), sh_u[h * HR + r], t);
            sh[tid] = t; __syncthreads();
            if (tid < CPB) {
                float T = sh[tid] + sh[tid + CPB];
                sh_v[tid] = (1.0f / NC) / (T + 1e-16f);
            }
            __syncthreads();
        } // c==2 / c==52: v already produced in fp32 by FUSED_ERR

        PHASE_C(par);
        par ^= 1;

        if (c == 51) {
            FUSED_ERR(done);
            if (done) return;
        }
    }

    // ===== cap exit (cpt=100): loss with u_100, v_100 =====
    {
        float la = 0.0f;
        #pragma unroll 8
        for (int r = 0; r < HR; ++r) {
            float m = __ldcs(&Mj[(size_t)r * NC]);
            float k = __expf(-20.0f * m);
            la = fmaf(k * m, sh_u[h * HR + r], la);
        }
        sh[tid] = la; __syncthreads();
        float lossj = 0.0f;
        if (tid < CPB) lossj = sh_v[tid] * (sh[tid] + sh[tid + CPB]);
        __syncthreads();
        float lb = blockReduce1024(lossj, sh);
        if (tid == 0) g_lossPart[bid] = lb;
        gsync(phase);
        if (bid == 0) {
            float lp = (tid < GRID) ? __ldcg(&g_lossPart[tid]) : 0.0f;
            float lt = blockReduce1024(lp, sh);
            if (tid == 0) out[0] = 100.0f * lt;
        }
        gsync(phase);
    }
}

extern "C" void kernel_launch(void* const* d_in, const int* in_sizes, int n_in,
                              void* d_out, int out_size) {
    const float* M = (const float*)d_in[0];
    float* out = (float*)d_out;
    sinkhorn_all<<<GRID, TPB>>>(M, out);
}

// round 6
// speedup vs baseline: 1.9509x; 1.9509x over previous
#include <cuda_runtime.h>
#include <cuda_fp16.h>

// M is [512, 65536] fp32. Sinkhorn; trip count in {1, 51, 100}; this input exits at 1.
// Fast path (trip-1) never materializes K: exp(-20M) is recomputed from M, which is
// ~L2-resident (128MB vs 126MB L2) after the first streaming pass.
#define NR    512
#define NC    65536
#define GRID  128              // <= SM count: wave-1 co-residency guaranteed
#define TPB   512              // R3-proven config (86 regs, no cap)
#define CPB   512              // columns per block (full column stripe)

// Persistent scratch (__device__ globals per allocation rule)
__device__ __half   g_K[(size_t)NR * NC];       // fp16 K: built ONLY on the c>=2 fallback
__device__ float    g_sPart[2][GRID * NR];      // parity-double-buffered row partials
__device__ float    g_errPart[GRID];
__device__ float    g_lossPart[GRID];
__device__ int      g_done;
__device__ unsigned g_bar = 0;
__device__ volatile unsigned g_gen = 0;         // monotone across graph replays

// Grid barrier: GRID <= #SMs -> cannot deadlock. Spin cap = escape hatch only.
__device__ __forceinline__ void gsync(unsigned &phase) {
    __syncthreads();
    if (threadIdx.x == 0) {
        ++phase;
        __threadfence();
        if (atomicAdd(&g_bar, 1u) == GRID - 1u) {
            g_bar = 0u;
            __threadfence();
            g_gen = phase;
        } else {
            unsigned spins = 0;
            while (g_gen < phase) {
                __nanosleep(64);
                if (++spins > (1u << 18)) break;
            }
        }
    }
    __syncthreads();
}

__device__ __forceinline__ float blockReduce512(float x, float* sh) {
    const int t = threadIdx.x;
    sh[t] = x; __syncthreads();
    if (t < 256) sh[t] += sh[t + 256];
    __syncthreads();
    if (t < 128) sh[t] += sh[t + 128];
    __syncthreads();
    if (t < 64)  sh[t] += sh[t + 64];
    __syncthreads();
    if (t < 32) {
        float v = sh[t] + sh[t + 32];
        #pragma unroll
        for (int o = 16; o; o >>= 1) v += __shfl_down_sync(0xffffffffu, v, o);
        if (t == 0) sh[0] = v;
    }
    __syncthreads();
    float r = sh[0];
    __syncthreads();
    return r;
}

__global__ void __launch_bounds__(TPB, 1)
sinkhorn_all(const float* __restrict__ M, float* __restrict__ out) {
    __shared__ float sh[TPB];
    __shared__ float sh2[TPB];
    __shared__ float sh_u[NR];
    __shared__ float sh_v[CPB];
    const int tid = threadIdx.x;
    const int bid = blockIdx.x;
    unsigned phase = g_gen;                   // continue barrier generation across replays

    const int    j  = bid * CPB + tid;        // owned column
    const float* Mj = M + j;
    const int    w    = tid >> 5;
    const int    lane = tid & 31;

    float v;                                  // v_j of current iteration (register)

    // ===== pass 1 (c=1 phase A): t_j = (1/NR) * sum_i exp(-20 M_ij); seeds L2 =====
    {
        float t = 0.0f;
        #pragma unroll 16
        for (int r = 0; r < NR; ++r)
            t += __expf(-20.0f * Mj[(size_t)r * NC]);
        v = (1.0f / NC) / (t * (1.0f / NR) + 1e-16f);
    }

    // ---- phase C over M (fast path): s_i = sum_{j in stripe} exp(-20 M_ij) v_j ----
    // Warp owns 32 rows; reads the block's 1MB M stripe (expected L2-hit).
    // Then one gsync; every block reduces the full u locally from g_sPart.
    #define PHASE_C_M(par)                                                         \
    {                                                                              \
        sh_v[tid] = v; __syncthreads();                                            \
        _Pragma("unroll 2")                                                        \
        for (int rr = 0; rr < 32; ++rr) {                                          \
            const int row = w * 32 + rr;                                           \
            const float4* mrow = (const float4*)(M + (size_t)row * NC + bid * CPB);\
            const float4* v4   = (const float4*)sh_v;                              \
            float s = 0.0f;                                                        \
            _Pragma("unroll")                                                      \
            for (int c = lane; c < 128; c += 32) {                                 \
                float4 m4 = mrow[c];                                               \
                float4 vv = v4[c];                                                 \
                s = fmaf(__expf(-20.0f * m4.x), vv.x, s);                          \
                s = fmaf(__expf(-20.0f * m4.y), vv.y, s);                          \
                s = fmaf(__expf(-20.0f * m4.z), vv.z, s);                          \
                s = fmaf(__expf(-20.0f * m4.w), vv.w, s);                          \
            }                                                                      \
            _Pragma("unroll")                                                      \
            for (int o = 16; o; o >>= 1) s += __shfl_down_sync(0xffffffffu, s, o); \
            if (lane == 0) g_sPart[par][bid * NR + row] = s;                       \
        }                                                                          \
        gsync(phase);                                                              \
        {                                                                          \
            float su = 0.0f;                                                       \
            _Pragma("unroll 8")                                                    \
            for (int b = 0; b < GRID; ++b)                                         \
                su += __ldcg(&g_sPart[par][b * NR + tid]);                         \
            sh_u[tid] = (1.0f / NR) / (su + 1e-16f);                               \
            __syncthreads();                                                       \
        }                                                                          \
    }

    // ---- phase C over fp16 K (fallback path, c>=2) ----
    #define PHASE_C_K(par)                                                         \
    {                                                                              \
        sh_v[tid] = v; __syncthreads();                                            \
        _Pragma("unroll 2")                                                        \
        for (int rr = 0; rr < 32; ++rr) {                                          \
            const int row = w * 32 + rr;                                           \
            const uint4* kp = (const uint4*)(g_K + (size_t)row * NC + bid * CPB);  \
            const float4* v4 = (const float4*)sh_v;                                \
            float s = 0.0f;                                                        \
            _Pragma("unroll")                                                      \
            for (int c = lane; c < 64; c += 32) {                                  \
                uint4 kk = kp[c];                                                  \
                const __half2* kh = (const __half2*)&kk;                           \
                float4 va = v4[2 * c], vb = v4[2 * c + 1];                         \
                float2 k0 = __half22float2(kh[0]);                                 \
                float2 k1 = __half22float2(kh[1]);                                 \
                float2 k2 = __half22float2(kh[2]);                                 \
                float2 k3 = __half22float2(kh[3]);                                 \
                s = fmaf(k0.x, va.x, s); s = fmaf(k0.y, va.y, s);                  \
                s = fmaf(k1.x, va.z, s); s = fmaf(k1.y, va.w, s);                  \
                s = fmaf(k2.x, vb.x, s); s = fmaf(k2.y, vb.y, s);                  \
                s = fmaf(k3.x, vb.z, s); s = fmaf(k3.y, vb.w, s);                  \
            }                                                                      \
            _Pragma("unroll")                                                      \
            for (int o = 16; o; o >>= 1) s += __shfl_down_sync(0xffffffffu, s, o); \
            if (lane == 0) g_sPart[par][bid * NR + row] = s;                       \
        }                                                                          \
        gsync(phase);                                                              \
        {                                                                          \
            float su = 0.0f;                                                       \
            _Pragma("unroll 8")                                                    \
            for (int b = 0; b < GRID; ++b)                                         \
                su += __ldcg(&g_sPart[par][b * NR + tid]);                         \
            sh_u[tid] = (1.0f / NR) / (su + 1e-16f);                               \
            __syncthreads();                                                       \
        }                                                                          \
    }

    // ---- fused err+loss (fp32 exp from M): t' = K^T u; err; loss. If converged,
    // block 0 writes out; else v <- b/(t'+eps) becomes the next v (fp32-exact).
    #define FUSED_ERR(done_var)                                                    \
    {                                                                              \
        float tp = 0.0f, la = 0.0f;                                                \
        _Pragma("unroll 16")                                                       \
        for (int r = 0; r < NR; ++r) {                                             \
            float m = Mj[(size_t)r * NC];                                          \
            float k = __expf(-20.0f * m);                                          \
            float u = sh_u[r];                                                     \
            tp = fmaf(k, u, tp);                                                   \
            la = fmaf(k * m, u, la);                                               \
        }                                                                          \
        float eb = blockReduce512(fabsf(v * tp - (1.0f / NC)), sh);                \
        float lb = blockReduce512(v * la, sh2);                                    \
        if (tid == 0) { g_errPart[bid] = eb; g_lossPart[bid] = lb; }               \
        float vn = (1.0f / NC) / (tp + 1e-16f);                                    \
        gsync(phase);                                                              \
        if (bid == 0) {                                                            \
            float ep = (tid < GRID) ? __ldcg(&g_errPart[tid]) : 0.0f;              \
            float et = blockReduce512(ep, sh);                                     \
            int dn = (et <= 0.005f);                                               \
            if (dn) {                                                              \
                float lp = (tid < GRID) ? __ldcg(&g_lossPart[tid]) : 0.0f;         \
                float lt = blockReduce512(lp, sh);                                 \
                if (tid == 0) out[0] = 100.0f * lt;                                \
            }                                                                      \
            if (tid == 0) g_done = dn;                                             \
        }                                                                          \
        gsync(phase);                                                              \
        v = vn;                                                                    \
        done_var = __ldcg(&g_done);                                                \
    }

    // ===== c = 1: phase C -> u_1; err check fused with loss (3 gsyncs total) =====
    PHASE_C_M(0);
    int done;
    FUSED_ERR(done);
    if (done) return;                         // trip-1 fast path ends here

    // ===== fallback (c >= 2): build fp16 K once, then iterate =====
    {
        __half* Kj = g_K + j;
        #pragma unroll 8
        for (int r = 0; r < NR; ++r)
            Kj[(size_t)r * NC] = __float2half(__expf(-20.0f * Mj[(size_t)r * NC]));
        __syncthreads();                      // K is block-local (own column stripe)
    }

    for (int c = 2; c <= 100; ++c) {
        if (c > 2 && c != 52) {
            // phase A: t_j = sum_i K_ij u_i (fp16 K, own column); v_j = b/(t+eps)
            float t = 0.0f;
            const __half* kc = g_K + j;
            #pragma unroll 16
            for (int r = 0; r < NR; ++r)
                t = fmaf(__half2float(kc[(size_t)r * NC]), sh_u[r], t);
            v = (1.0f / NC) / (t + 1e-16f);
        } // c==2 / c==52: v already produced in fp32 by FUSED_ERR

        PHASE_C_K(c & 1);                     // u_c

        if (c == 51) {
            FUSED_ERR(done);
            if (done) return;
        }
    }

    // ===== cap exit (cpt=100): loss with u_100, v_100 =====
    {
        float la = 0.0f;
        #pragma unroll 8
        for (int r = 0; r < NR; ++r) {
            float m = Mj[(size_t)r * NC];
            float k = __expf(-20.0f * m);
            la = fmaf(k * m, sh_u[r], la);
        }
        float lb = blockReduce512(v * la, sh);
        if (tid == 0) g_lossPart[bid] = lb;
        gsync(phase);
        if (bid == 0) {
            float lp = (tid < GRID) ? __ldcg(&g_lossPart[tid]) : 0.0f;
            float lt = blockReduce512(lp, sh);
            if (tid == 0) out[0] = 100.0f * lt;
        }
        gsync(phase);
    }
}

extern "C" void kernel_launch(void* const* d_in, const int* in_sizes, int n_in,
                              void* d_out, int out_size) {
    const float* M = (const float*)d_in[0];
    float* out = (float*)d_out;
    sinkhorn_all<<<GRID, TPB>>>(M, out);
}